// round 17
// baseline (speedup 1.0000x reference)
#include <cuda_runtime.h>
#include <cuda_fp16.h>
#include <math.h>
#include <stdint.h>

#define BB 2
#define SS 2048
#define EE 256
#define HH 32

// log2(e)/sqrt(8): folded into the Q fragment.
#define CSCALE 0.51006972790221780093f

__device__ uint32_t g_attnh[BB * SS * EE / 2];  // attention output, fp16x2 [B,S,E]
__device__ uint4 g_qh[64 * 2048];               // fp16 cos(x+theta): 8 vals (16B) per (bh,s)
__device__ uint32_t g_wh[EE * EE / 2];          // W pre-converted to fp16x2

// Warp-level fp16 MMA m16n8k16, D/C fp32. Baseline sm_80 PTX.
__device__ __forceinline__ void mma16816(float d[4],
    uint32_t a0, uint32_t a1, uint32_t a2, uint32_t a3,
    uint32_t b0, uint32_t b1, const float c[4])
{
    asm volatile("mma.sync.aligned.m16n8k16.row.col.f32.f16.f16.f32 "
        "{%0,%1,%2,%3}, {%4,%5,%6,%7}, {%8,%9}, {%10,%11,%12,%13};"
        : "=f"(d[0]), "=f"(d[1]), "=f"(d[2]), "=f"(d[3])
        : "r"(a0), "r"(a1), "r"(a2), "r"(a3), "r"(b0), "r"(b1),
          "f"(c[0]), "f"(c[1]), "f"(c[2]), "f"(c[3]));
}
// Warp-level fp16 MMA m16n8k8 with FP16 accumulator: D packed f16x2.
__device__ __forceinline__ void mma16808h(uint32_t& d0, uint32_t& d1,
    uint32_t a0, uint32_t a1, uint32_t b0)
{
    asm volatile("mma.sync.aligned.m16n8k8.row.col.f16.f16.f16.f16 "
        "{%0,%1}, {%2,%3}, {%4}, {%5,%6};"
        : "=r"(d0), "=r"(d1)
        : "r"(a0), "r"(a1), "r"(b0), "r"(0u), "r"(0u));
}

// ---------------------------------------------------------------------------
// Prep: blocks 0..511  -> q = cos(x+theta) fp16 via smem transpose.
//       blocks 512..543 -> W fp32 -> fp16.
// ---------------------------------------------------------------------------
__global__ __launch_bounds__(256) void prep_kernel(
    const float* __restrict__ x,
    const float* __restrict__ theta,
    const float* __restrict__ W)
{
    const int t   = threadIdx.x;
    const int blk = blockIdx.x;

    if (blk >= 512) {
#pragma unroll
        for (int l = 0; l < 2; l++) {
            int i4 = (blk - 512) * 512 + l * 256 + t;   // float4 index
            float4 v = *reinterpret_cast<const float4*>(W + i4 * 4);
            half2 h0 = __floats2half2_rn(v.x, v.y);
            half2 h1 = __floats2half2_rn(v.z, v.w);
            uint2 pk = make_uint2(*reinterpret_cast<uint32_t*>(&h0),
                                  *reinterpret_cast<uint32_t*>(&h1));
            *reinterpret_cast<uint2*>(g_wh + i4 * 2) = pk;
        }
        return;
    }

    __shared__ uint2 tile[32][18];       // [h][s_local*2 + hf]
    const int b   = blk >> 8;
    const int s0  = (blk & 255) << 3;    // 8 tokens
    float th[8];
#pragma unroll
    for (int d = 0; d < 8; d++) th[d] = __ldg(theta + d);

    const float* xb = x + ((size_t)b * SS + s0) * EE;
#pragma unroll
    for (int l = 0; l < 2; l++) {
        int idx = t + l * 256;
        int row = idx >> 6;
        int c4  = idx & 63;
        float4 v = *reinterpret_cast<const float4*>(xb + (size_t)row * EE + c4 * 4);
        int hf = c4 & 1;
        int db = hf * 4;
        half2 h0 = __floats2half2_rn(__cosf(v.x + th[db + 0]), __cosf(v.y + th[db + 1]));
        half2 h1 = __floats2half2_rn(__cosf(v.z + th[db + 2]), __cosf(v.w + th[db + 3]));
        tile[c4 >> 1][row * 2 + hf] =
            make_uint2(*reinterpret_cast<uint32_t*>(&h0),
                       *reinterpret_cast<uint32_t*>(&h1));
    }
    __syncthreads();
#pragma unroll
    for (int l = 0; l < 2; l++) {
        int idx = t + l * 256;
        int h  = idx >> 4;
        int in = idx & 15;
        uint2 v = tile[h][in];
        uint2* dst = reinterpret_cast<uint2*>(g_qh + (((b << 5) + h) << 11) + s0);
        dst[in] = v;
    }
}

// ---------------------------------------------------------------------------
// Warp-MMA flash attention (R12, byte-identical — proven tensor floor).
// ---------------------------------------------------------------------------
__global__ __launch_bounds__(256, 4) void attn_kernel(const int* __restrict__ mask)
{
    __shared__ uint4    sK[2][128];
    __shared__ uint32_t sMaskP[2][64];
    __shared__ uint32_t sVT[2][8][68];

    const int tid  = threadIdx.x;
    const int wid  = tid >> 5;
    const int lane = tid & 31;
    const int r = lane >> 2;
    const int m = lane & 3;
    const int bh = blockIdx.x >> 4;
    const int qt = blockIdx.x & 15;
    const int b  = bh >> 5;

    const int qbase = (bh << 11) + (qt << 7) + wid * 16;
    const uint32_t* qw = reinterpret_cast<const uint32_t*>(g_qh + qbase);
    uint32_t a0r = qw[r * 4 + m];
    uint32_t a1r = qw[(r + 8) * 4 + m];
    float2 f0 = __half22float2(*reinterpret_cast<half2*>(&a0r));
    float2 f1 = __half22float2(*reinterpret_cast<half2*>(&a1r));
    half2 s0 = __floats2half2_rn(f0.x * CSCALE, f0.y * CSCALE);
    half2 s1 = __floats2half2_rn(f1.x * CSCALE, f1.y * CSCALE);
    const uint32_t a0 = *reinterpret_cast<uint32_t*>(&s0);
    const uint32_t a1 = *reinterpret_cast<uint32_t*>(&s1);

    float O[4] = {0.f, 0.f, 0.f, 0.f};
    float l_lo = 0.f, l_hi = 0.f;

    auto load_chunk = [&](int c, int buf) {
        const int kg = (bh << 11) + (c << 7);
        if (tid < 128) {
            sK[buf][tid] = g_qh[kg + tid];
            if (tid < 64) {
                int2 mm = *reinterpret_cast<const int2*>(
                    mask + b * SS + (c << 7) + 2 * tid);
                sMaskP[buf][tid] = (mm.x ? 0x0000FFFFu : 0u) |
                                   (mm.y ? 0xFFFF0000u : 0u);
            }
        } else {
            int u  = (tid - 128) >> 1;
            int hf = tid & 1;
            const uint32_t* ka = reinterpret_cast<const uint32_t*>(g_qh + kg + 2 * u);
            const uint32_t* kb = ka + 4;
            uint32_t ua0 = ka[hf * 2], ua1 = ka[hf * 2 + 1];
            uint32_t ub0 = kb[hf * 2], ub1 = kb[hf * 2 + 1];
            sVT[buf][hf * 4 + 0][u] = __byte_perm(ua0, ub0, 0x5410);
            sVT[buf][hf * 4 + 1][u] = __byte_perm(ua0, ub0, 0x7632);
            sVT[buf][hf * 4 + 2][u] = __byte_perm(ua1, ub1, 0x5410);
            sVT[buf][hf * 4 + 3][u] = __byte_perm(ua1, ub1, 0x7632);
        }
    };

    load_chunk(0, 0);
    __syncthreads();

    for (int c = 0; c < 16; c++) {
        const int buf = c & 1;
        if (c < 15) load_chunk(c + 1, buf ^ 1);

        const uint32_t* k32 = reinterpret_cast<const uint32_t*>(sK[buf]);

#pragma unroll
        for (int t = 0; t < 8; t++) {
            uint32_t P00, P01, P10, P11;
            {
                int key = 16 * t + r;
                uint32_t kb0 = k32[key * 4 + m];
                uint32_t d0, d1;
                mma16808h(d0, d1, a0, a1, kb0);
                asm("ex2.approx.f16x2 %0, %1;" : "=r"(P00) : "r"(d0));
                asm("ex2.approx.f16x2 %0, %1;" : "=r"(P01) : "r"(d1));
                uint32_t w = sMaskP[buf][8 * t + m];
                P00 &= w;
                P01 &= w;
                float2 fa = __half22float2(*reinterpret_cast<half2*>(&P00));
                float2 fb = __half22float2(*reinterpret_cast<half2*>(&P01));
                l_lo += fa.x + fa.y;
                l_hi += fb.x + fb.y;
            }
            {
                int key = 16 * t + 8 + r;
                uint32_t kb0 = k32[key * 4 + m];
                uint32_t d0, d1;
                mma16808h(d0, d1, a0, a1, kb0);
                asm("ex2.approx.f16x2 %0, %1;" : "=r"(P10) : "r"(d0));
                asm("ex2.approx.f16x2 %0, %1;" : "=r"(P11) : "r"(d1));
                uint32_t w = sMaskP[buf][8 * t + 4 + m];
                P10 &= w;
                P11 &= w;
                float2 fa = __half22float2(*reinterpret_cast<half2*>(&P10));
                float2 fb = __half22float2(*reinterpret_cast<half2*>(&P11));
                l_lo += fa.x + fa.y;
                l_hi += fb.x + fb.y;
            }
            uint32_t vb0 = sVT[buf][r][t * 8 + m];
            uint32_t vb1 = sVT[buf][r][t * 8 + 4 + m];
            mma16816(O, P00, P01, P10, P11, vb0, vb1, O);
        }
        __syncthreads();
    }

    l_lo += __shfl_xor_sync(0xffffffffu, l_lo, 1);
    l_lo += __shfl_xor_sync(0xffffffffu, l_lo, 2);
    l_hi += __shfl_xor_sync(0xffffffffu, l_hi, 1);
    l_hi += __shfl_xor_sync(0xffffffffu, l_hi, 2);
    float inv_lo = 1.0f / l_lo;
    float inv_hi = 1.0f / l_hi;

    const int h  = bh & 31;
    const int q0 = (qt << 7) + wid * 16 + r;
    uint32_t* op = g_attnh + ((size_t)b * SS + q0) * 128 + h * 4 + m;
    half2 o1 = __floats2half2_rn(O[0] * inv_lo, O[1] * inv_lo);
    half2 o2 = __floats2half2_rn(O[2] * inv_hi, O[3] * inv_hi);
    op[0]       = *reinterpret_cast<uint32_t*>(&o1);
    op[8 * 128] = *reinterpret_cast<uint32_t*>(&o2);
}

// ---------------------------------------------------------------------------
// Output projection: Y[4096,256] = A @ Wh^T + b via fp16 MMA.
// K-chunked (4x64) cp.async double-buffered pipeline; 36.9KB smem -> all
// 256 CTAs resident in one wave, staging overlapped with compute.
// ---------------------------------------------------------------------------
__global__ __launch_bounds__(256, 4) void proj_kernel(
    const float* __restrict__ bo,
    float*       __restrict__ Y)
{
    __shared__ uint32_t As[2][64][36];   // 64 rows x 32 u32 (64 fp16), pad 36
    __shared__ uint32_t Ws[2][64][36];

    const int tid = threadIdx.x;
    const int im0 = blockIdx.x * 64;
    const int jn0 = blockIdx.y * 64;

    auto stage = [&](int kc4, int buf) {
#pragma unroll
        for (int l = 0; l < 2; l++) {
            int idx = l * 256 + tid;     // 0..511
            int row = idx >> 3, q4 = (idx & 7) * 4;
            const void* ga = g_attnh + (size_t)(im0 + row) * 128 + kc4 * 32 + q4;
            uint32_t sa = (uint32_t)__cvta_generic_to_shared(&As[buf][row][q4]);
            asm volatile("cp.async.cg.shared.global [%0], [%1], 16;"
                         :: "r"(sa), "l"(ga));
            const void* gw = g_wh + (size_t)(jn0 + row) * 128 + kc4 * 32 + q4;
            uint32_t sw = (uint32_t)__cvta_generic_to_shared(&Ws[buf][row][q4]);
            asm volatile("cp.async.cg.shared.global [%0], [%1], 16;"
                         :: "r"(sw), "l"(gw));
        }
        asm volatile("cp.async.commit_group;");
    };

    const int lane = tid & 31, wid = tid >> 5;
    const int r = lane >> 2, m = lane & 3;
    const int mb  = (wid & 3) * 16;      // m-block
    const int nb0 = (wid >> 2) * 32;     // 4 n8-blocks

    float acc[4][4];
#pragma unroll
    for (int nn = 0; nn < 4; nn++)
#pragma unroll
        for (int i = 0; i < 4; i++) acc[nn][i] = 0.f;

    stage(0, 0);

    for (int c = 0; c < 4; c++) {
        const int buf = c & 1;
        if (c < 3) {
            stage(c + 1, buf ^ 1);
            asm volatile("cp.async.wait_group 1;");
        } else {
            asm volatile("cp.async.wait_group 0;");
        }
        __syncthreads();

#pragma unroll
        for (int kcl = 0; kcl < 4; kcl++) {
            uint32_t a0 = As[buf][mb + r][kcl * 8 + m];
            uint32_t a1 = As[buf][mb + r + 8][kcl * 8 + m];
            uint32_t a2 = As[buf][mb + r][kcl * 8 + 4 + m];
            uint32_t a3 = As[buf][mb + r + 8][kcl * 8 + 4 + m];
#pragma unroll
            for (int nn = 0; nn < 4; nn++) {
                uint32_t b0 = Ws[buf][nb0 + nn * 8 + r][kcl * 8 + m];
                uint32_t b1 = Ws[buf][nb0 + nn * 8 + r][kcl * 8 + 4 + m];
                mma16816(acc[nn], a0, a1, a2, a3, b0, b1, acc[nn]);
            }
        }
        __syncthreads();
    }

    // Epilogue: bias + fp32 stores
#pragma unroll
    for (int nn = 0; nn < 4; nn++) {
        int j = jn0 + nb0 + nn * 8 + 2 * m;
        float2 bv = *reinterpret_cast<const float2*>(bo + j);
        int i0 = im0 + mb + r;
        *reinterpret_cast<float2*>(Y + (size_t)i0 * 256 + j) =
            make_float2(acc[nn][0] + bv.x, acc[nn][1] + bv.y);
        *reinterpret_cast<float2*>(Y + (size_t)(i0 + 8) * 256 + j) =
            make_float2(acc[nn][2] + bv.x, acc[nn][3] + bv.y);
    }
}

// ---------------------------------------------------------------------------
extern "C" void kernel_launch(void* const* d_in, const int* in_sizes, int n_in,
                              void* d_out, int out_size)
{
    const float* x     = (const float*)d_in[0];
    const int*   mask  = (const int*)d_in[1];
    const float* theta = (const float*)d_in[2];
    const float* W     = (const float*)d_in[3];
    const float* bo    = (const float*)d_in[4];
    float*       out   = (float*)d_out;

    prep_kernel<<<544, 256>>>(x, theta, W);
    attn_kernel<<<64 * 16, 256>>>(mask);

    dim3 grid(BB * SS / 64, EE / 64);  // (64, 4)
    proj_kernel<<<grid, 256>>>(bo, out);
}